// round 1
// baseline (speedup 1.0000x reference)
#include <cuda_runtime.h>

#define B 16
#define S 512
#define IN_DIM 64
#define D 64
#define HDIM 256
#define L 32
#define TY 256
#define TX 287
#define QC 16
#define KT 32
#define NS_MAX 16

// ---------------- scratch (static device arrays; no allocation) ----------------
__device__ float g_q[B*S*D];
__device__ float g_k[B*S*D];
__device__ float g_G[(size_t)B*S*L*L];   // 33.5 MB
__device__ float g_C[B*S*L];
__device__ float g_lossbt[B*NS_MAX];
__device__ int   g_valid[B*NS_MAX];

// ---------------- K1: MLP -> layernorm -> tanh -> e_orig, q, k ----------------
__global__ __launch_bounds__(256) void k_mlp(
    const float* __restrict__ fps, const float* __restrict__ W1, const float* __restrict__ b1,
    const float* __restrict__ gamma, const float* __restrict__ beta,
    const float* __restrict__ W2, const float* __restrict__ b2,
    const float* __restrict__ Wq, const float* __restrict__ bq,
    const float* __restrict__ Wk, const float* __restrict__ bk,
    float* __restrict__ eorig)
{
    int bs = blockIdx.x;
    int s  = bs & (S-1);
    int tid = threadIdx.x;
    int lane = tid & 31, wid = tid >> 5;
    __shared__ float xf[IN_DIM];
    __shared__ float th[HDIM];
    __shared__ float part[4][D];
    __shared__ float er[D];
    __shared__ float red[8];

    if (tid < IN_DIM) xf[tid] = fps[bs*IN_DIM + tid];
    __syncthreads();

    float h = b1[tid];
    #pragma unroll
    for (int i = 0; i < IN_DIM; i++) h = fmaf(xf[i], W1[i*HDIM + tid], h);

    // mean
    float v = h;
    #pragma unroll
    for (int o = 16; o; o >>= 1) v += __shfl_xor_sync(0xffffffffu, v, o);
    if (lane == 0) red[wid] = v;
    __syncthreads();
    float tot = 0.f;
    #pragma unroll
    for (int w = 0; w < 8; w++) tot += red[w];
    float mu = tot * (1.0f/HDIM);
    __syncthreads();
    // var
    float dcen = h - mu;
    v = dcen*dcen;
    #pragma unroll
    for (int o = 16; o; o >>= 1) v += __shfl_xor_sync(0xffffffffu, v, o);
    if (lane == 0) red[wid] = v;
    __syncthreads();
    tot = 0.f;
    #pragma unroll
    for (int w = 0; w < 8; w++) tot += red[w];
    float var = tot * (1.0f/HDIM);

    float hn = dcen * rsqrtf(var + 1e-5f) * gamma[tid] + beta[tid];
    th[tid] = tanhf(hn);
    __syncthreads();

    // second GEMV: 256 threads split 4-way over the 256 inner dim
    int oj = tid & (D-1);
    int p  = tid >> 6;
    float acc = 0.f;
    #pragma unroll
    for (int i = 0; i < 64; i++) {
        int ii = p*64 + i;
        acc = fmaf(th[ii], W2[ii*D + oj], acc);
    }
    part[p][oj] = acc;
    __syncthreads();

    if (tid < D) {
        float eo = tanhf(part[0][tid]+part[1][tid]+part[2][tid]+part[3][tid] + b2[tid]);
        eorig[bs*D + tid] = eo;
        int pidx = tid >> 1;
        float dv = expf(-(float)(2*pidx) * (9.210340371976184f/64.0f));
        float ang = (float)s * dv;
        float pe = (tid & 1) ? cosf(ang) : sinf(ang);
        er[tid] = eo + 0.05f * pe;
    }
    __syncthreads();

    if (tid < 2*D) {
        int j = tid & (D-1);
        const float* W  = (tid < D) ? Wq : Wk;
        const float* bb = (tid < D) ? bq : bk;
        float a = bb[j];
        #pragma unroll
        for (int i = 0; i < D; i++) a = fmaf(er[i], W[i*D + j], a);
        if (tid < D) g_q[bs*D + j] = a; else g_k[bs*D + j] = a;
    }
}

// ---------------- K2: causal attention softmax -> alpha (output) ----------------
__global__ __launch_bounds__(256) void k_attn(float* __restrict__ alpha)
{
    int b  = blockIdx.y;
    int q0 = blockIdx.x * QC;
    int tid = threadIdx.x;
    __shared__ float qs[QC*D];
    __shared__ float ks[KT][68];
    __shared__ float sc[QC][S];

    {
        const float4* src = (const float4*)(g_q + (b*S + q0)*D);
        float4* dst = (float4*)qs;
        dst[tid] = src[tid];               // QC*D/4 == 256
    }
    int smax = q0 + QC - 1;
    int qi = tid >> 4;
    int kj = tid & 15;

    for (int t0 = 0; t0 <= smax; t0 += KT) {
        const float4* src = (const float4*)(g_k + (b*S + t0)*D);
        #pragma unroll
        for (int u = 0; u < 2; u++) {
            int i = tid + u*256;           // KT*D/4 == 512
            int r = i >> 4, c = i & 15;
            ((float4*)ks[r])[c] = src[i];
        }
        __syncthreads();

        float a0 = 0.f, a1 = 0.f;
        const float4* q4 = (const float4*)(qs + qi*D);
        const float4* ka = (const float4*)(ks[kj]);
        const float4* kb = (const float4*)(ks[kj+16]);
        #pragma unroll
        for (int i = 0; i < D/4; i++) {
            float4 qv = q4[i];
            float4 va = ka[i];
            float4 vb = kb[i];
            a0 = fmaf(qv.x, va.x, a0); a0 = fmaf(qv.y, va.y, a0);
            a0 = fmaf(qv.z, va.z, a0); a0 = fmaf(qv.w, va.w, a0);
            a1 = fmaf(qv.x, vb.x, a1); a1 = fmaf(qv.y, vb.y, a1);
            a1 = fmaf(qv.z, vb.z, a1); a1 = fmaf(qv.w, vb.w, a1);
        }
        int sq = q0 + qi;
        int ta = t0 + kj, tb = t0 + kj + 16;
        // scores/sqrt(64) * 2.0  == dot * 0.25
        sc[qi][ta] = (ta <= sq) ? a0*0.25f : -1e30f;
        sc[qi][tb] = (tb <= sq) ? a1*0.25f : -1e30f;
        __syncthreads();
    }

    int lane = tid & 31, wid = tid >> 5;
    for (int qq = wid; qq < QC; qq += 8) {
        int sq = q0 + qq;
        int n = sq + 1;
        float mx = -1e30f;
        for (int t = lane; t < n; t += 32) mx = fmaxf(mx, sc[qq][t]);
        #pragma unroll
        for (int o = 16; o; o >>= 1) mx = fmaxf(mx, __shfl_xor_sync(0xffffffffu, mx, o));
        float sum = 0.f;
        for (int t = lane; t < n; t += 32) {
            float e2 = expf(sc[qq][t] - mx);
            sc[qq][t] = e2;
            sum += e2;
        }
        #pragma unroll
        for (int o = 16; o; o >>= 1) sum += __shfl_xor_sync(0xffffffffu, sum, o);
        float inv = 1.f/sum;
        float* arow = alpha + ((size_t)(b*S + sq))*S;
        for (int t = lane; t < S; t += 32) arow[t] = (t < n) ? sc[qq][t]*inv : 0.f;
    }
}

// ---------------- K3: windowed Gram (sliding autocorrelation) + cross ----------------
__global__ __launch_bounds__(256) void k_gram(const float* __restrict__ x, const float* __restrict__ y)
{
    int bs = blockIdx.x;
    int tid = threadIdx.x;
    int lane = tid & 31, wid = tid >> 5;
    __shared__ float xs[TX];
    __shared__ float ys[TY];
    for (int i = tid; i < TX; i += 256) xs[i] = x[(size_t)bs*TX + i];
    ys[tid] = y[(size_t)bs*TY + tid];
    __syncthreads();

    float* Gp = g_G + (size_t)bs*(L*L);
    for (int d = wid; d < L; d += 8) {
        // S_d(0) = sum_k x[k]*x[k+d]
        float p = 0.f;
        for (int kk = lane; kk < TY; kk += 32) p = fmaf(xs[kk], xs[kk+d], p);
        #pragma unroll
        for (int o = 16; o; o >>= 1) p += __shfl_xor_sync(0xffffffffu, p, o);
        // delta_{lane-1}; valid only where needed (lane + d <= 31)
        float delta = 0.f;
        if (lane >= 1 && lane + d <= 31) {
            int jj = lane - 1;
            delta = xs[jj+TY]*xs[jj+TY+d] - xs[jj]*xs[jj+d];
        }
        #pragma unroll
        for (int o = 1; o < 32; o <<= 1) {
            float nb = __shfl_up_sync(0xffffffffu, delta, o);
            if (lane >= o) delta += nb;
        }
        float Sl = p + delta;                  // S_d(lane)
        int l = lane, m = lane + d;
        if (m < L) {
            Gp[l*L + m] = Sl;
            if (d) Gp[m*L + l] = Sl;
        }
    }
    float* Cp = g_C + (size_t)bs*L;
    for (int l = wid; l < L; l += 8) {
        float p = 0.f;
        for (int kk = lane; kk < TY; kk += 32) p = fmaf(xs[kk+l], ys[kk], p);
        #pragma unroll
        for (int o = 16; o; o >>= 1) p += __shfl_xor_sync(0xffffffffu, p, o);
        if (lane == 0) Cp[l] = p;
    }
}

// ---------------- K4: per (b,t) weighted gram, SPD solve, loss_bt ----------------
__global__ __launch_bounds__(256) void k_solve(
    const float* __restrict__ x, const float* __restrict__ y,
    const int* __restrict__ steps, const float* __restrict__ alpha, int nsamp)
{
    int b = blockIdx.y;
    int t = blockIdx.x;
    int tid = threadIdx.x;
    int st = steps[t];
    __shared__ float wm[S];
    __shared__ int anyv;
    __shared__ float A[L][L+2];
    __shared__ float wt[L];
    __shared__ float xw[TX];
    __shared__ float red[8];

    if (tid == 0) anyv = 0;
    __syncthreads();
    const float* arow = alpha + ((size_t)(b*S + st))*S;
    int local_any = 0;
    for (int s2 = tid; s2 < S; s2 += 256) {
        float a = arow[s2];
        float w = (a > 0.005f) ? a : 0.f;
        wm[s2] = w;
        if (w > 0.f) local_any = 1;
    }
    if (local_any) atomicOr(&anyv, 1);
    __syncthreads();

    // weighted gram: each thread owns flat entries tid, tid+256, tid+512, tid+768
    float g0 = 0, g1 = 0, g2 = 0, g3 = 0;
    const float* Gb = g_G + (size_t)b*S*(L*L);
    for (int s2 = 0; s2 < S; s2++) {
        float w = wm[s2];
        if (w == 0.f) continue;                // uniform branch, deterministic order
        const float* Gs = Gb + (size_t)s2*(L*L);
        g0 = fmaf(w, Gs[tid],       g0);
        g1 = fmaf(w, Gs[tid + 256], g1);
        g2 = fmaf(w, Gs[tid + 512], g2);
        g3 = fmaf(w, Gs[tid + 768], g3);
    }
    {
        int i0 = tid;       A[i0>>5][i0&31] = g0 + (((i0>>5)==(i0&31)) ? 0.01f : 0.f);
        i0 = tid + 256;     A[i0>>5][i0&31] = g1 + (((i0>>5)==(i0&31)) ? 0.01f : 0.f);
        i0 = tid + 512;     A[i0>>5][i0&31] = g2 + (((i0>>5)==(i0&31)) ? 0.01f : 0.f);
        i0 = tid + 768;     A[i0>>5][i0&31] = g3 + (((i0>>5)==(i0&31)) ? 0.01f : 0.f);
    }
    if (tid < 32) {
        float c = 0.f;
        const float* Cb = g_C + (size_t)b*S*L;
        for (int s2 = 0; s2 < S; s2++) {
            float w = wm[s2];
            if (w != 0.f) c = fmaf(w, Cb[s2*L + tid], c);
        }
        A[tid][L] = c;
    }
    __syncthreads();

    // warp-0 Gauss-Jordan on SPD (gram + ridge*I)
    if (tid < 32) {
        int i = tid;
        for (int kk = 0; kk < L; kk++) {
            float f = A[i][kk] / A[kk][kk];
            __syncwarp();
            if (i != kk) {
                for (int j2 = kk; j2 <= L; j2++) A[i][j2] = fmaf(-f, A[kk][j2], A[i][j2]);
            }
            __syncwarp();
        }
        wt[i] = A[i][L] / A[i][i];
    }
    for (int i = tid; i < TX; i += 256) xw[i] = x[(size_t)(b*S + st)*TX + i];
    __syncthreads();

    float pred = 0.f;
    #pragma unroll
    for (int l2 = 0; l2 < L; l2++) pred = fmaf(xw[tid + l2], wt[l2], pred);
    float err = y[(size_t)(b*S + st)*TY + tid] - pred;
    float v = err*err;
    #pragma unroll
    for (int o = 16; o; o >>= 1) v += __shfl_xor_sync(0xffffffffu, v, o);
    int lane = tid & 31, wid2 = tid >> 5;
    if (lane == 0) red[wid2] = v;
    __syncthreads();
    if (tid == 0) {
        float tt = 0.f;
        #pragma unroll
        for (int w = 0; w < 8; w++) tt += red[w];
        g_lossbt[b*nsamp + t] = tt * (1.0f/TY);
        g_valid[b*nsamp + t] = anyv;
    }
}

// ---------------- K5: deterministic final reduction ----------------
__global__ void k_final(float* __restrict__ out, int n)
{
    if (threadIdx.x == 0 && blockIdx.x == 0) {
        float tot = 0.f; int cnt = 0;
        for (int i = 0; i < n; i++) {
            if (g_valid[i]) { tot += g_lossbt[i]; cnt++; }
        }
        out[0] = tot / (float)(cnt > 0 ? cnt : 1);
    }
}

// ---------------- launch ----------------
extern "C" void kernel_launch(void* const* d_in, const int* in_sizes, int n_in,
                              void* d_out, int out_size)
{
    const float* fps   = (const float*)d_in[0];
    const float* x     = (const float*)d_in[1];
    const float* y     = (const float*)d_in[2];
    const int*   steps = (const int*)  d_in[3];
    const float* W1    = (const float*)d_in[4];
    const float* b1    = (const float*)d_in[5];
    const float* gamma = (const float*)d_in[6];
    const float* beta  = (const float*)d_in[7];
    const float* W2    = (const float*)d_in[8];
    const float* b2    = (const float*)d_in[9];
    const float* Wq    = (const float*)d_in[10];
    const float* bq    = (const float*)d_in[11];
    const float* Wk    = (const float*)d_in[12];
    const float* bk    = (const float*)d_in[13];
    float* out = (float*)d_out;

    int nsamp = in_sizes[3];
    if (nsamp > NS_MAX) nsamp = NS_MAX;

    float* alpha = out + 1;
    float* eorig = out + 1 + (size_t)B*S*S;

    k_mlp <<< B*S, 256 >>>(fps, W1, b1, gamma, beta, W2, b2, Wq, bq, Wk, bk, eorig);
    k_attn<<< dim3(S/QC, B), 256 >>>(alpha);
    k_gram<<< B*S, 256 >>>(x, y);
    k_solve<<< dim3(nsamp, B), 256 >>>(x, y, steps, alpha, nsamp);
    k_final<<< 1, 32 >>>(out, B*nsamp);
}

// round 2
// speedup vs baseline: 1.2325x; 1.2325x over previous
#include <cuda_runtime.h>

#define B 16
#define S 512
#define IN_DIM 64
#define D 64
#define HDIM 256
#define L 32
#define TY 256
#define TX 287
#define QC 16
#define KT 32
#define NS_MAX 16
#define POSB 32          // positions per k_mlp block
#define MLP_SMEM_FLOATS (16384+16384+4096+4096+2048+8192+2048+3*256+3*64)

// ---------------- scratch (static device arrays; no allocation) ----------------
__device__ float g_q[B*S*D];
__device__ float g_k[B*S*D];
__device__ float g_G[(size_t)B*S*L*L];   // 33.5 MB
__device__ float g_C[B*S*L];
__device__ float g_lossbt[B*NS_MAX];
__device__ int   g_valid[B*NS_MAX];

// ---------------- K1: MLP -> LN -> tanh -> e_orig, q, k (weights in smem) ----------------
__global__ __launch_bounds__(256, 1) void k_mlp(
    const float* __restrict__ fps, const float* __restrict__ W1, const float* __restrict__ b1,
    const float* __restrict__ gamma, const float* __restrict__ beta,
    const float* __restrict__ W2, const float* __restrict__ b2,
    const float* __restrict__ Wq, const float* __restrict__ bq,
    const float* __restrict__ Wk, const float* __restrict__ bk,
    float* __restrict__ eorig)
{
    extern __shared__ float sm[];
    float* W1s = sm;                  // 64*256
    float* W2s = W1s + 64*256;        // 256*64
    float* Wqs = W2s + 256*64;        // 64*64
    float* Wks = Wqs + 64*64;         // 64*64
    float* xs  = Wks + 64*64;         // POSB*64   = 2048
    float* ths = xs  + POSB*64;       // POSB*256  = 8192
    float* ers = ths + POSB*256;      // POSB*64   = 2048
    float* b1s = ers + POSB*64;       // 256
    float* gs  = b1s + 256;           // 256
    float* bes = gs  + 256;           // 256
    float* b2s = bes + 256;           // 64
    float* bqs = b2s + 64;            // 64
    float* bks = bqs + 64;            // 64

    int tid = threadIdx.x;
    int lane = tid & 31, wrp = tid >> 5;
    int gbase = blockIdx.x * POSB;    // global flat position base

    for (int i = tid; i < 64*256; i += 256) W1s[i] = W1[i];
    for (int i = tid; i < 256*64; i += 256) W2s[i] = W2[i];
    for (int i = tid; i < 64*64;  i += 256) { Wqs[i] = Wq[i]; Wks[i] = Wk[i]; }
    if (tid < 256) { b1s[tid] = b1[tid]; gs[tid] = gamma[tid]; bes[tid] = beta[tid]; }
    if (tid < 64)  { b2s[tid] = b2[tid]; bqs[tid] = bq[tid]; bks[tid] = bk[tid]; }
    for (int i = tid; i < POSB*64; i += 256) xs[i] = fps[(size_t)gbase*64 + i];
    __syncthreads();

    int p0 = wrp * 4;  // this warp's 4 positions (in-block index)

    // column constants for lane's 8 columns (lane + 32k)
    float b1k[8], gk[8], bek[8];
    #pragma unroll
    for (int k = 0; k < 8; k++) {
        int c = lane + 32*k;
        b1k[k] = b1s[c]; gk[k] = gs[c]; bek[k] = bes[c];
    }

    // GEMV1: h[p][k] = b1 + fps . W1
    float h[4][8];
    #pragma unroll
    for (int p = 0; p < 4; p++)
        #pragma unroll
        for (int k = 0; k < 8; k++) h[p][k] = b1k[k];

    for (int i = 0; i < 64; i++) {
        float wv8[8];
        #pragma unroll
        for (int k = 0; k < 8; k++) wv8[k] = W1s[i*256 + lane + 32*k];
        #pragma unroll
        for (int p = 0; p < 4; p++) {
            float xv = xs[(p0+p)*64 + i];
            #pragma unroll
            for (int k = 0; k < 8; k++) h[p][k] = fmaf(xv, wv8[k], h[p][k]);
        }
    }

    // layernorm + tanh per position
    #pragma unroll
    for (int p = 0; p < 4; p++) {
        float s = 0.f;
        #pragma unroll
        for (int k = 0; k < 8; k++) s += h[p][k];
        #pragma unroll
        for (int o = 16; o; o >>= 1) s += __shfl_xor_sync(0xffffffffu, s, o);
        float mu = s * (1.0f/HDIM);
        float v = 0.f;
        #pragma unroll
        for (int k = 0; k < 8; k++) { float dd = h[p][k] - mu; v += dd*dd; }
        #pragma unroll
        for (int o = 16; o; o >>= 1) v += __shfl_xor_sync(0xffffffffu, v, o);
        float rs = rsqrtf(v * (1.0f/HDIM) + 1e-5f);
        #pragma unroll
        for (int k = 0; k < 8; k++) {
            float t = tanhf((h[p][k]-mu)*rs*gk[k] + bek[k]);
            ths[(p0+p)*256 + lane + 32*k] = t;
        }
    }
    __syncwarp();

    // GEMV2: d[j] = b2 + tanh(h) . W2   (lane owns j0=lane, j1=lane+32)
    float d0[4], d1[4];
    #pragma unroll
    for (int p = 0; p < 4; p++) { d0[p] = b2s[lane]; d1[p] = b2s[lane+32]; }
    for (int ii = 0; ii < 256; ii += 4) {
        float w0[4], w1[4];
        #pragma unroll
        for (int u = 0; u < 4; u++) {
            w0[u] = W2s[(ii+u)*64 + lane];
            w1[u] = W2s[(ii+u)*64 + lane + 32];
        }
        #pragma unroll
        for (int p = 0; p < 4; p++) {
            float4 tv = *(const float4*)&ths[(p0+p)*256 + ii];
            d0[p] = fmaf(tv.x, w0[0], d0[p]); d1[p] = fmaf(tv.x, w1[0], d1[p]);
            d0[p] = fmaf(tv.y, w0[1], d0[p]); d1[p] = fmaf(tv.y, w1[1], d1[p]);
            d0[p] = fmaf(tv.z, w0[2], d0[p]); d1[p] = fmaf(tv.z, w1[2], d1[p]);
            d0[p] = fmaf(tv.w, w0[3], d0[p]); d1[p] = fmaf(tv.w, w1[3], d1[p]);
        }
    }

    // e_orig + positional encoding
    int pidx0 = lane >> 1;
    int pidx1 = (lane+32) >> 1;
    const float M = 9.210340371976184f / 64.0f;  // ln(10000)/64
    float dv0 = expf(-(float)(2*pidx0) * M);
    float dv1 = expf(-(float)(2*pidx1) * M);
    #pragma unroll
    for (int p = 0; p < 4; p++) {
        int gp = gbase + p0 + p;
        int seq = gp & (S-1);
        float e0 = tanhf(d0[p]);
        float e1 = tanhf(d1[p]);
        eorig[(size_t)gp*64 + lane]      = e0;
        eorig[(size_t)gp*64 + lane + 32] = e1;
        float a0 = (float)seq * dv0;
        float a1 = (float)seq * dv1;
        float pe0 = (lane & 1) ? cosf(a0) : sinf(a0);
        float pe1 = ((lane+32) & 1) ? cosf(a1) : sinf(a1);
        ers[(p0+p)*64 + lane]      = e0 + 0.05f*pe0;
        ers[(p0+p)*64 + lane + 32] = e1 + 0.05f*pe1;
    }
    __syncwarp();

    // q/k GEMVs
    float q0a[4], q1a[4], k0a[4], k1a[4];
    #pragma unroll
    for (int p = 0; p < 4; p++) {
        q0a[p] = bqs[lane]; q1a[p] = bqs[lane+32];
        k0a[p] = bks[lane]; k1a[p] = bks[lane+32];
    }
    for (int i = 0; i < 64; i++) {
        float wq0 = Wqs[i*64+lane], wq1 = Wqs[i*64+lane+32];
        float wk0 = Wks[i*64+lane], wk1 = Wks[i*64+lane+32];
        #pragma unroll
        for (int p = 0; p < 4; p++) {
            float ev = ers[(p0+p)*64 + i];
            q0a[p] = fmaf(ev, wq0, q0a[p]); q1a[p] = fmaf(ev, wq1, q1a[p]);
            k0a[p] = fmaf(ev, wk0, k0a[p]); k1a[p] = fmaf(ev, wk1, k1a[p]);
        }
    }
    #pragma unroll
    for (int p = 0; p < 4; p++) {
        int gp = gbase + p0 + p;
        g_q[(size_t)gp*64 + lane]      = q0a[p];
        g_q[(size_t)gp*64 + lane + 32] = q1a[p];
        g_k[(size_t)gp*64 + lane]      = k0a[p];
        g_k[(size_t)gp*64 + lane + 32] = k1a[p];
    }
}

// ---------------- K2: causal attention softmax -> alpha (output) ----------------
__global__ __launch_bounds__(256) void k_attn(float* __restrict__ alpha)
{
    int b  = blockIdx.y;
    int q0 = blockIdx.x * QC;
    int tid = threadIdx.x;
    __shared__ float qs[QC*D];
    __shared__ float ks[KT][68];
    __shared__ float sc[QC][S];

    {
        const float4* src = (const float4*)(g_q + (b*S + q0)*D);
        float4* dst = (float4*)qs;
        dst[tid] = src[tid];
    }
    int smax = q0 + QC - 1;
    int qi = tid >> 4;
    int kj = tid & 15;

    for (int t0 = 0; t0 <= smax; t0 += KT) {
        const float4* src = (const float4*)(g_k + (b*S + t0)*D);
        #pragma unroll
        for (int u = 0; u < 2; u++) {
            int i = tid + u*256;
            int r = i >> 4, c = i & 15;
            ((float4*)ks[r])[c] = src[i];
        }
        __syncthreads();

        float a0 = 0.f, a1 = 0.f;
        const float4* q4 = (const float4*)(qs + qi*D);
        const float4* ka = (const float4*)(ks[kj]);
        const float4* kb = (const float4*)(ks[kj+16]);
        #pragma unroll
        for (int i = 0; i < D/4; i++) {
            float4 qv = q4[i];
            float4 va = ka[i];
            float4 vb = kb[i];
            a0 = fmaf(qv.x, va.x, a0); a0 = fmaf(qv.y, va.y, a0);
            a0 = fmaf(qv.z, va.z, a0); a0 = fmaf(qv.w, va.w, a0);
            a1 = fmaf(qv.x, vb.x, a1); a1 = fmaf(qv.y, vb.y, a1);
            a1 = fmaf(qv.z, vb.z, a1); a1 = fmaf(qv.w, vb.w, a1);
        }
        int sq = q0 + qi;
        int ta = t0 + kj, tb = t0 + kj + 16;
        sc[qi][ta] = (ta <= sq) ? a0*0.25f : -1e30f;
        sc[qi][tb] = (tb <= sq) ? a1*0.25f : -1e30f;
        __syncthreads();
    }

    int lane = tid & 31, wid = tid >> 5;
    for (int qq = wid; qq < QC; qq += 8) {
        int sq = q0 + qq;
        int n = sq + 1;
        float mx = -1e30f;
        for (int t = lane; t < n; t += 32) mx = fmaxf(mx, sc[qq][t]);
        #pragma unroll
        for (int o = 16; o; o >>= 1) mx = fmaxf(mx, __shfl_xor_sync(0xffffffffu, mx, o));
        float sum = 0.f;
        for (int t = lane; t < n; t += 32) {
            float e2 = __expf(sc[qq][t] - mx);
            sc[qq][t] = e2;
            sum += e2;
        }
        #pragma unroll
        for (int o = 16; o; o >>= 1) sum += __shfl_xor_sync(0xffffffffu, sum, o);
        float inv = 1.f/sum;
        float* arow = alpha + ((size_t)(b*S + sq))*S;
        for (int t = lane; t < S; t += 32) arow[t] = (t < n) ? sc[qq][t]*inv : 0.f;
    }
}

// ---------------- K3: windowed Gram (sliding autocorrelation) + cross ----------------
__global__ __launch_bounds__(256) void k_gram(const float* __restrict__ x, const float* __restrict__ y)
{
    int bs = blockIdx.x;
    int tid = threadIdx.x;
    int lane = tid & 31, wid = tid >> 5;
    __shared__ float xs[TX];
    __shared__ float ys[TY];
    for (int i = tid; i < TX; i += 256) xs[i] = x[(size_t)bs*TX + i];
    ys[tid] = y[(size_t)bs*TY + tid];
    __syncthreads();

    float* Gp = g_G + (size_t)bs*(L*L);
    for (int d = wid; d < L; d += 8) {
        float p = 0.f;
        for (int kk = lane; kk < TY; kk += 32) p = fmaf(xs[kk], xs[kk+d], p);
        #pragma unroll
        for (int o = 16; o; o >>= 1) p += __shfl_xor_sync(0xffffffffu, p, o);
        float delta = 0.f;
        if (lane >= 1 && lane + d <= 31) {
            int jj = lane - 1;
            delta = xs[jj+TY]*xs[jj+TY+d] - xs[jj]*xs[jj+d];
        }
        #pragma unroll
        for (int o = 1; o < 32; o <<= 1) {
            float nb = __shfl_up_sync(0xffffffffu, delta, o);
            if (lane >= o) delta += nb;
        }
        float Sl = p + delta;
        int l = lane, m = lane + d;
        if (m < L) {
            Gp[l*L + m] = Sl;
            if (d) Gp[m*L + l] = Sl;
        }
    }
    float* Cp = g_C + (size_t)bs*L;
    for (int l = wid; l < L; l += 8) {
        float p = 0.f;
        for (int kk = lane; kk < TY; kk += 32) p = fmaf(xs[kk+l], ys[kk], p);
        #pragma unroll
        for (int o = 16; o; o >>= 1) p += __shfl_xor_sync(0xffffffffu, p, o);
        if (lane == 0) Cp[l] = p;
    }
}

// ---------------- K4: per (b,t) weighted gram, SPD solve, loss_bt ----------------
__global__ __launch_bounds__(1024) void k_solve(
    const float* __restrict__ x, const float* __restrict__ y,
    const int* __restrict__ steps, const float* __restrict__ alpha, int nsamp)
{
    int b = blockIdx.y;
    int t = blockIdx.x;
    int tid = threadIdx.x;
    int lane = tid & 31, wrp = tid >> 5;
    int st = steps[t];
    __shared__ float wv[S];
    __shared__ int   sidx[S];
    __shared__ int   wcnt[17];
    __shared__ float A[L][L+2];
    __shared__ float wt[L];
    __shared__ float xw[TX];
    __shared__ float red[8];

    // ---- deterministic (order-preserving) compaction of nonzero weights ----
    const float* arow = alpha + ((size_t)(b*S + st))*S;
    float a = 0.f; int flag = 0;
    if (tid < S) { a = arow[tid]; flag = (a > 0.005f) ? 1 : 0; }
    unsigned ball = __ballot_sync(0xffffffffu, flag != 0);
    if (tid < S && lane == 0) wcnt[wrp] = __popc(ball);
    __syncthreads();
    if (tid == 0) {
        int acc = 0;
        #pragma unroll
        for (int i = 0; i < 16; i++) { int c = wcnt[i]; wcnt[i] = acc; acc += c; }
        wcnt[16] = acc;
    }
    __syncthreads();
    if (tid < S && flag) {
        int pos = wcnt[wrp] + __popc(ball & ((1u << lane) - 1u));
        wv[pos] = a; sidx[pos] = tid;
    }
    __syncthreads();
    int nnz = wcnt[16];

    // ---- dense accumulation over compacted list: 1 gram entry per thread ----
    float acc = 0.f;
    const float* Gb = g_G + (size_t)b*S*(L*L);
    int j = 0;
    for (; j + 4 <= nnz; j += 4) {
        int s0 = sidx[j], s1 = sidx[j+1], s2 = sidx[j+2], s3 = sidx[j+3];
        float w0 = wv[j], w1 = wv[j+1], w2 = wv[j+2], w3 = wv[j+3];
        float v0 = Gb[(size_t)s0*(L*L) + tid];
        float v1 = Gb[(size_t)s1*(L*L) + tid];
        float v2 = Gb[(size_t)s2*(L*L) + tid];
        float v3 = Gb[(size_t)s3*(L*L) + tid];
        acc = fmaf(w0, v0, acc);
        acc = fmaf(w1, v1, acc);
        acc = fmaf(w2, v2, acc);
        acc = fmaf(w3, v3, acc);
    }
    for (; j < nnz; j++) acc = fmaf(wv[j], Gb[(size_t)sidx[j]*(L*L) + tid], acc);

    A[tid >> 5][tid & 31] = acc + (((tid >> 5) == (tid & 31)) ? 0.01f : 0.f);

    if (tid < 32) {
        float c = 0.f;
        const float* Cb = g_C + (size_t)b*S*L;
        for (int jj = 0; jj < nnz; jj++) c = fmaf(wv[jj], Cb[sidx[jj]*L + tid], c);
        A[tid][L] = c;
    }
    for (int i = tid; i < TX; i += 1024) xw[i] = x[(size_t)(b*S + st)*TX + i];
    __syncthreads();

    // warp-0 Gauss-Jordan on (gram + ridge*I)
    if (tid < 32) {
        int i = tid;
        for (int kk = 0; kk < L; kk++) {
            float f = A[i][kk] / A[kk][kk];
            __syncwarp();
            if (i != kk) {
                for (int j2 = kk; j2 <= L; j2++) A[i][j2] = fmaf(-f, A[kk][j2], A[i][j2]);
            }
            __syncwarp();
        }
        wt[i] = A[i][L] / A[i][i];
    }
    __syncthreads();

    if (tid < TY) {
        float pred = 0.f;
        #pragma unroll
        for (int l2 = 0; l2 < L; l2++) pred = fmaf(xw[tid + l2], wt[l2], pred);
        float err = y[(size_t)(b*S + st)*TY + tid] - pred;
        float v = err*err;
        #pragma unroll
        for (int o = 16; o; o >>= 1) v += __shfl_xor_sync(0xffffffffu, v, o);
        if (lane == 0) red[wrp] = v;
    }
    __syncthreads();
    if (tid == 0) {
        float tt = 0.f;
        #pragma unroll
        for (int w = 0; w < 8; w++) tt += red[w];
        g_lossbt[b*nsamp + t] = tt * (1.0f/TY);
        g_valid[b*nsamp + t] = (nnz > 0) ? 1 : 0;
    }
}

// ---------------- K5: deterministic final reduction ----------------
__global__ void k_final(float* __restrict__ out, int n)
{
    if (threadIdx.x == 0 && blockIdx.x == 0) {
        float tot = 0.f; int cnt = 0;
        for (int i = 0; i < n; i++) {
            if (g_valid[i]) { tot += g_lossbt[i]; cnt++; }
        }
        out[0] = tot / (float)(cnt > 0 ? cnt : 1);
    }
}

// ---------------- launch ----------------
extern "C" void kernel_launch(void* const* d_in, const int* in_sizes, int n_in,
                              void* d_out, int out_size)
{
    const float* fps   = (const float*)d_in[0];
    const float* x     = (const float*)d_in[1];
    const float* y     = (const float*)d_in[2];
    const int*   steps = (const int*)  d_in[3];
    const float* W1    = (const float*)d_in[4];
    const float* b1    = (const float*)d_in[5];
    const float* gamma = (const float*)d_in[6];
    const float* beta  = (const float*)d_in[7];
    const float* W2    = (const float*)d_in[8];
    const float* b2    = (const float*)d_in[9];
    const float* Wq    = (const float*)d_in[10];
    const float* bq    = (const float*)d_in[11];
    const float* Wk    = (const float*)d_in[12];
    const float* bk    = (const float*)d_in[13];
    float* out = (float*)d_out;

    int nsamp = in_sizes[3];
    if (nsamp > NS_MAX) nsamp = NS_MAX;

    float* alpha = out + 1;
    float* eorig = out + 1 + (size_t)B*S*S;

    size_t mlp_smem = (size_t)MLP_SMEM_FLOATS * sizeof(float);
    cudaFuncSetAttribute(k_mlp, cudaFuncAttributeMaxDynamicSharedMemorySize, (int)mlp_smem);

    k_mlp <<< (B*S)/POSB, 256, mlp_smem >>>(fps, W1, b1, gamma, beta, W2, b2, Wq, bq, Wk, bk, eorig);
    k_attn<<< dim3(S/QC, B), 256 >>>(alpha);
    k_gram<<< B*S, 256 >>>(x, y);
    k_solve<<< dim3(nsamp, B), 1024 >>>(x, y, steps, alpha, nsamp);
    k_final<<< 1, 32 >>>(out, B*nsamp);
}

// round 3
// speedup vs baseline: 1.2581x; 1.0207x over previous
#include <cuda_runtime.h>

#define B 16
#define S 512
#define IN_DIM 64
#define D 64
#define HDIM 256
#define L 32
#define TY 256
#define TX 287
#define QC 16
#define KT 32
#define NS_MAX 16
#define CH 8              // split-K chunks for weighted gram
#define SCH (S/CH)        // 64 s-values per chunk
#define POSB 32           // positions per k_mlp block
#define MLP_SMEM_FLOATS (16384+16384+4096+4096+2048+8192+2048+3*256+3*64)

// ---------------- scratch (static device arrays; no allocation) ----------------
__device__ float g_q[B*S*D];
__device__ float g_k[B*S*D];
__device__ float g_G[(size_t)B*S*L*L];   // 33.5 MB
__device__ float g_C[B*S*L];
__device__ float g_pA[(size_t)B*NS_MAX*CH*(L*L + L)];  // partial gram+cross
__device__ int   g_pany[B*NS_MAX*CH];
__device__ float g_lossbt[B*NS_MAX];
__device__ int   g_valid[B*NS_MAX];

// ---------------- K1: MLP -> LN -> tanh -> e_orig, q, k (weights in smem) ----------------
__global__ __launch_bounds__(256, 1) void k_mlp(
    const float* __restrict__ fps, const float* __restrict__ W1, const float* __restrict__ b1,
    const float* __restrict__ gamma, const float* __restrict__ beta,
    const float* __restrict__ W2, const float* __restrict__ b2,
    const float* __restrict__ Wq, const float* __restrict__ bq,
    const float* __restrict__ Wk, const float* __restrict__ bk,
    float* __restrict__ eorig)
{
    extern __shared__ float sm[];
    float* W1s = sm;                  // 64*256
    float* W2s = W1s + 64*256;        // 256*64
    float* Wqs = W2s + 256*64;        // 64*64
    float* Wks = Wqs + 64*64;         // 64*64
    float* xs  = Wks + 64*64;         // POSB*64
    float* ths = xs  + POSB*64;       // POSB*256
    float* ers = ths + POSB*256;      // POSB*64
    float* b1s = ers + POSB*64;       // 256
    float* gs  = b1s + 256;
    float* bes = gs  + 256;
    float* b2s = bes + 256;
    float* bqs = b2s + 64;
    float* bks = bqs + 64;

    int tid = threadIdx.x;
    int lane = tid & 31, wrp = tid >> 5;
    int gbase = blockIdx.x * POSB;

    for (int i = tid; i < 64*256; i += 256) W1s[i] = W1[i];
    for (int i = tid; i < 256*64; i += 256) W2s[i] = W2[i];
    for (int i = tid; i < 64*64;  i += 256) { Wqs[i] = Wq[i]; Wks[i] = Wk[i]; }
    if (tid < 256) { b1s[tid] = b1[tid]; gs[tid] = gamma[tid]; bes[tid] = beta[tid]; }
    if (tid < 64)  { b2s[tid] = b2[tid]; bqs[tid] = bq[tid]; bks[tid] = bk[tid]; }
    for (int i = tid; i < POSB*64; i += 256) xs[i] = fps[(size_t)gbase*64 + i];
    __syncthreads();

    int p0 = wrp * 4;

    float b1k[8], gk[8], bek[8];
    #pragma unroll
    for (int k = 0; k < 8; k++) {
        int c = lane + 32*k;
        b1k[k] = b1s[c]; gk[k] = gs[c]; bek[k] = bes[c];
    }

    float h[4][8];
    #pragma unroll
    for (int p = 0; p < 4; p++)
        #pragma unroll
        for (int k = 0; k < 8; k++) h[p][k] = b1k[k];

    for (int i = 0; i < 64; i++) {
        float wv8[8];
        #pragma unroll
        for (int k = 0; k < 8; k++) wv8[k] = W1s[i*256 + lane + 32*k];
        #pragma unroll
        for (int p = 0; p < 4; p++) {
            float xv = xs[(p0+p)*64 + i];
            #pragma unroll
            for (int k = 0; k < 8; k++) h[p][k] = fmaf(xv, wv8[k], h[p][k]);
        }
    }

    #pragma unroll
    for (int p = 0; p < 4; p++) {
        float s = 0.f;
        #pragma unroll
        for (int k = 0; k < 8; k++) s += h[p][k];
        #pragma unroll
        for (int o = 16; o; o >>= 1) s += __shfl_xor_sync(0xffffffffu, s, o);
        float mu = s * (1.0f/HDIM);
        float v = 0.f;
        #pragma unroll
        for (int k = 0; k < 8; k++) { float dd = h[p][k] - mu; v += dd*dd; }
        #pragma unroll
        for (int o = 16; o; o >>= 1) v += __shfl_xor_sync(0xffffffffu, v, o);
        float rs = rsqrtf(v * (1.0f/HDIM) + 1e-5f);
        #pragma unroll
        for (int k = 0; k < 8; k++) {
            float t = tanhf((h[p][k]-mu)*rs*gk[k] + bek[k]);
            ths[(p0+p)*256 + lane + 32*k] = t;
        }
    }
    __syncwarp();

    float d0[4], d1[4];
    #pragma unroll
    for (int p = 0; p < 4; p++) { d0[p] = b2s[lane]; d1[p] = b2s[lane+32]; }
    for (int ii = 0; ii < 256; ii += 4) {
        float w0[4], w1[4];
        #pragma unroll
        for (int u = 0; u < 4; u++) {
            w0[u] = W2s[(ii+u)*64 + lane];
            w1[u] = W2s[(ii+u)*64 + lane + 32];
        }
        #pragma unroll
        for (int p = 0; p < 4; p++) {
            float4 tv = *(const float4*)&ths[(p0+p)*256 + ii];
            d0[p] = fmaf(tv.x, w0[0], d0[p]); d1[p] = fmaf(tv.x, w1[0], d1[p]);
            d0[p] = fmaf(tv.y, w0[1], d0[p]); d1[p] = fmaf(tv.y, w1[1], d1[p]);
            d0[p] = fmaf(tv.z, w0[2], d0[p]); d1[p] = fmaf(tv.z, w1[2], d1[p]);
            d0[p] = fmaf(tv.w, w0[3], d0[p]); d1[p] = fmaf(tv.w, w1[3], d1[p]);
        }
    }

    int pidx0 = lane >> 1;
    int pidx1 = (lane+32) >> 1;
    const float M = 9.210340371976184f / 64.0f;
    float dv0 = expf(-(float)(2*pidx0) * M);
    float dv1 = expf(-(float)(2*pidx1) * M);
    #pragma unroll
    for (int p = 0; p < 4; p++) {
        int gp = gbase + p0 + p;
        int seq = gp & (S-1);
        float e0 = tanhf(d0[p]);
        float e1 = tanhf(d1[p]);
        eorig[(size_t)gp*64 + lane]      = e0;
        eorig[(size_t)gp*64 + lane + 32] = e1;
        float a0 = (float)seq * dv0;
        float a1 = (float)seq * dv1;
        float pe0 = (lane & 1) ? cosf(a0) : sinf(a0);
        float pe1 = ((lane+32) & 1) ? cosf(a1) : sinf(a1);
        ers[(p0+p)*64 + lane]      = e0 + 0.05f*pe0;
        ers[(p0+p)*64 + lane + 32] = e1 + 0.05f*pe1;
    }
    __syncwarp();

    float q0a[4], q1a[4], k0a[4], k1a[4];
    #pragma unroll
    for (int p = 0; p < 4; p++) {
        q0a[p] = bqs[lane]; q1a[p] = bqs[lane+32];
        k0a[p] = bks[lane]; k1a[p] = bks[lane+32];
    }
    for (int i = 0; i < 64; i++) {
        float wq0 = Wqs[i*64+lane], wq1 = Wqs[i*64+lane+32];
        float wk0 = Wks[i*64+lane], wk1 = Wks[i*64+lane+32];
        #pragma unroll
        for (int p = 0; p < 4; p++) {
            float ev = ers[(p0+p)*64 + i];
            q0a[p] = fmaf(ev, wq0, q0a[p]); q1a[p] = fmaf(ev, wq1, q1a[p]);
            k0a[p] = fmaf(ev, wk0, k0a[p]); k1a[p] = fmaf(ev, wk1, k1a[p]);
        }
    }
    #pragma unroll
    for (int p = 0; p < 4; p++) {
        int gp = gbase + p0 + p;
        g_q[(size_t)gp*64 + lane]      = q0a[p];
        g_q[(size_t)gp*64 + lane + 32] = q1a[p];
        g_k[(size_t)gp*64 + lane]      = k0a[p];
        g_k[(size_t)gp*64 + lane + 32] = k1a[p];
    }
}

// ---------------- K2: causal attention softmax -> alpha (q in registers) ----------------
__global__ __launch_bounds__(256, 2) void k_attn(float* __restrict__ alpha)
{
    int b  = blockIdx.y;
    int q0 = blockIdx.x * QC;
    int tid = threadIdx.x;
    __shared__ float qs[QC*D];
    __shared__ float ks[KT][68];
    __shared__ float sc[QC][S];

    {
        const float4* src = (const float4*)(g_q + (b*S + q0)*D);
        float4* dst = (float4*)qs;
        dst[tid] = src[tid];
    }
    __syncthreads();

    int smax = q0 + QC - 1;
    int qi = tid >> 4;
    int kj = tid & 15;

    // hoist this thread's q row into registers
    float4 qr[16];
    {
        const float4* q4 = (const float4*)(qs + qi*D);
        #pragma unroll
        for (int i = 0; i < 16; i++) qr[i] = q4[i];
    }

    for (int t0 = 0; t0 <= smax; t0 += KT) {
        const float4* src = (const float4*)(g_k + (b*S + t0)*D);
        #pragma unroll
        for (int u = 0; u < 2; u++) {
            int i = tid + u*256;
            int r = i >> 4, c = i & 15;
            ((float4*)ks[r])[c] = src[i];
        }
        __syncthreads();

        float a0 = 0.f, a1 = 0.f;
        const float4* ka = (const float4*)(ks[kj]);
        const float4* kb = (const float4*)(ks[kj+16]);
        #pragma unroll
        for (int i = 0; i < 16; i++) {
            float4 qv = qr[i];
            float4 va = ka[i];
            float4 vb = kb[i];
            a0 = fmaf(qv.x, va.x, a0); a0 = fmaf(qv.y, va.y, a0);
            a0 = fmaf(qv.z, va.z, a0); a0 = fmaf(qv.w, va.w, a0);
            a1 = fmaf(qv.x, vb.x, a1); a1 = fmaf(qv.y, vb.y, a1);
            a1 = fmaf(qv.z, vb.z, a1); a1 = fmaf(qv.w, vb.w, a1);
        }
        int sq = q0 + qi;
        int ta = t0 + kj, tb = t0 + kj + 16;
        sc[qi][ta] = (ta <= sq) ? a0*0.25f : -1e30f;
        sc[qi][tb] = (tb <= sq) ? a1*0.25f : -1e30f;
        __syncthreads();
    }

    int lane = tid & 31, wid = tid >> 5;
    for (int qq = wid; qq < QC; qq += 8) {
        int sq = q0 + qq;
        int n = sq + 1;
        float mx = -1e30f;
        for (int t = lane; t < n; t += 32) mx = fmaxf(mx, sc[qq][t]);
        #pragma unroll
        for (int o = 16; o; o >>= 1) mx = fmaxf(mx, __shfl_xor_sync(0xffffffffu, mx, o));
        float sum = 0.f;
        for (int t = lane; t < n; t += 32) {
            float e2 = __expf(sc[qq][t] - mx);
            sc[qq][t] = e2;
            sum += e2;
        }
        #pragma unroll
        for (int o = 16; o; o >>= 1) sum += __shfl_xor_sync(0xffffffffu, sum, o);
        float inv = 1.f/sum;
        float* arow = alpha + ((size_t)(b*S + sq))*S;
        for (int t = lane; t < S; t += 32) arow[t] = (t < n) ? sc[qq][t]*inv : 0.f;
    }
}

// ---------------- K3: windowed Gram (sliding autocorrelation) + cross ----------------
__global__ __launch_bounds__(256) void k_gram(const float* __restrict__ x, const float* __restrict__ y)
{
    int bs = blockIdx.x;
    int tid = threadIdx.x;
    int lane = tid & 31, wid = tid >> 5;
    __shared__ float xs[TX];
    __shared__ float ys[TY];
    for (int i = tid; i < TX; i += 256) xs[i] = x[(size_t)bs*TX + i];
    ys[tid] = y[(size_t)bs*TY + tid];
    __syncthreads();

    float* Gp = g_G + (size_t)bs*(L*L);
    for (int d = wid; d < L; d += 8) {
        float p = 0.f;
        for (int kk = lane; kk < TY; kk += 32) p = fmaf(xs[kk], xs[kk+d], p);
        #pragma unroll
        for (int o = 16; o; o >>= 1) p += __shfl_xor_sync(0xffffffffu, p, o);
        float delta = 0.f;
        if (lane >= 1 && lane + d <= 31) {
            int jj = lane - 1;
            delta = xs[jj+TY]*xs[jj+TY+d] - xs[jj]*xs[jj+d];
        }
        #pragma unroll
        for (int o = 1; o < 32; o <<= 1) {
            float nb = __shfl_up_sync(0xffffffffu, delta, o);
            if (lane >= o) delta += nb;
        }
        float Sl = p + delta;
        int l = lane, m = lane + d;
        if (m < L) {
            Gp[l*L + m] = Sl;
            if (d) Gp[m*L + l] = Sl;
        }
    }
    float* Cp = g_C + (size_t)bs*L;
    for (int l = wid; l < L; l += 8) {
        float p = 0.f;
        for (int kk = lane; kk < TY; kk += 32) p = fmaf(xs[kk+l], ys[kk], p);
        #pragma unroll
        for (int o = 16; o; o >>= 1) p += __shfl_xor_sync(0xffffffffu, p, o);
        if (lane == 0) Cp[l] = p;
    }
}

// ---------------- K4a: partial weighted gram over a 64-s chunk ----------------
__global__ __launch_bounds__(256) void k_wpart(
    const int* __restrict__ steps, const float* __restrict__ alpha, int nsamp)
{
    int t = blockIdx.x;
    int b = blockIdx.y;
    int c = blockIdx.z;
    int tid = threadIdx.x;
    int lane = tid & 31, wrp = tid >> 5;
    int st = steps[t];
    int s0 = c * SCH;

    __shared__ float wv[SCH];
    __shared__ int   sidx[SCH];
    __shared__ int   wcnt[3];

    // order-preserving compaction of this chunk's nonzero weights (2 warps)
    const float* arow = alpha + ((size_t)(b*S + st))*S + s0;
    float a = 0.f; int flag = 0;
    if (tid < SCH) { a = arow[tid]; flag = (a > 0.005f) ? 1 : 0; }
    unsigned ball = __ballot_sync(0xffffffffu, flag != 0);
    if (tid < SCH && lane == 0) wcnt[wrp] = __popc(ball);
    __syncthreads();
    if (tid == 0) { int c0 = wcnt[0]; wcnt[2] = c0 + wcnt[1]; wcnt[1] = c0; wcnt[0] = 0; }
    __syncthreads();
    if (tid < SCH && flag) {
        int pos = wcnt[wrp] + __popc(ball & ((1u << lane) - 1u));
        wv[pos] = a; sidx[pos] = s0 + tid;
    }
    __syncthreads();
    int nnz = wcnt[2];

    // dense accumulation: 4 gram entries per thread
    float g0 = 0.f, g1 = 0.f, g2 = 0.f, g3 = 0.f;
    const float* Gb = g_G + (size_t)b*S*(L*L);
    int j = 0;
    for (; j + 2 <= nnz; j += 2) {
        const float* Ga = Gb + (size_t)sidx[j]*(L*L);
        const float* Gc = Gb + (size_t)sidx[j+1]*(L*L);
        float wa = wv[j], wb = wv[j+1];
        g0 = fmaf(wa, Ga[tid],     g0); g0 = fmaf(wb, Gc[tid],     g0);
        g1 = fmaf(wa, Ga[tid+256], g1); g1 = fmaf(wb, Gc[tid+256], g1);
        g2 = fmaf(wa, Ga[tid+512], g2); g2 = fmaf(wb, Gc[tid+512], g2);
        g3 = fmaf(wa, Ga[tid+768], g3); g3 = fmaf(wb, Gc[tid+768], g3);
    }
    if (j < nnz) {
        const float* Ga = Gb + (size_t)sidx[j]*(L*L);
        float wa = wv[j];
        g0 = fmaf(wa, Ga[tid],     g0);
        g1 = fmaf(wa, Ga[tid+256], g1);
        g2 = fmaf(wa, Ga[tid+512], g2);
        g3 = fmaf(wa, Ga[tid+768], g3);
    }

    float* P = g_pA + (size_t)((b*nsamp + t)*CH + c)*(L*L + L);
    P[tid]     = g0;
    P[tid+256] = g1;
    P[tid+512] = g2;
    P[tid+768] = g3;

    if (tid < 32) {
        float cc = 0.f;
        const float* Cb = g_C + (size_t)b*S*L;
        for (int jj = 0; jj < nnz; jj++) cc = fmaf(wv[jj], Cb[sidx[jj]*L + tid], cc);
        P[L*L + tid] = cc;
    }
    if (tid == 0) g_pany[(b*nsamp + t)*CH + c] = (nnz > 0) ? 1 : 0;
}

// ---------------- K4b: reduce partials (fixed order), solve, loss ----------------
__global__ __launch_bounds__(256) void k_solve2(
    const float* __restrict__ x, const float* __restrict__ y,
    const int* __restrict__ steps, int nsamp)
{
    int t = blockIdx.x;
    int b = blockIdx.y;
    int tid = threadIdx.x;
    int lane = tid & 31, wrp = tid >> 5;
    int st = steps[t];

    __shared__ float A[L][L+2];
    __shared__ float wt[L];
    __shared__ float xw[TX];
    __shared__ float red[8];
    __shared__ int anyv;

    const float* Pb = g_pA + (size_t)(b*nsamp + t)*CH*(L*L + L);
    float g0 = 0.f, g1 = 0.f, g2 = 0.f, g3 = 0.f;
    #pragma unroll
    for (int c = 0; c < CH; c++) {   // fixed order: deterministic
        const float* P = Pb + (size_t)c*(L*L + L);
        g0 += P[tid];
        g1 += P[tid+256];
        g2 += P[tid+512];
        g3 += P[tid+768];
    }
    {
        int i0 = tid;      A[i0>>5][i0&31] = g0 + (((i0>>5)==(i0&31)) ? 0.01f : 0.f);
        i0 = tid + 256;    A[i0>>5][i0&31] = g1 + (((i0>>5)==(i0&31)) ? 0.01f : 0.f);
        i0 = tid + 512;    A[i0>>5][i0&31] = g2 + (((i0>>5)==(i0&31)) ? 0.01f : 0.f);
        i0 = tid + 768;    A[i0>>5][i0&31] = g3 + (((i0>>5)==(i0&31)) ? 0.01f : 0.f);
    }
    if (tid < 32) {
        float cc = 0.f;
        #pragma unroll
        for (int c = 0; c < CH; c++) cc += Pb[(size_t)c*(L*L + L) + L*L + tid];
        A[tid][L] = cc;
    }
    if (tid == 0) {
        int v = 0;
        const int* pa = g_pany + (b*nsamp + t)*CH;
        #pragma unroll
        for (int c = 0; c < CH; c++) v |= pa[c];
        anyv = v;
    }
    for (int i = tid; i < TX; i += 256) xw[i] = x[(size_t)(b*S + st)*TX + i];
    __syncthreads();

    if (tid < 32) {
        int i = tid;
        for (int kk = 0; kk < L; kk++) {
            float f = A[i][kk] / A[kk][kk];
            __syncwarp();
            if (i != kk) {
                for (int j2 = kk; j2 <= L; j2++) A[i][j2] = fmaf(-f, A[kk][j2], A[i][j2]);
            }
            __syncwarp();
        }
        wt[i] = A[i][L] / A[i][i];
    }
    __syncthreads();

    float pred = 0.f;
    #pragma unroll
    for (int l2 = 0; l2 < L; l2++) pred = fmaf(xw[tid + l2], wt[l2], pred);
    float err = y[(size_t)(b*S + st)*TY + tid] - pred;
    float v = err*err;
    #pragma unroll
    for (int o = 16; o; o >>= 1) v += __shfl_xor_sync(0xffffffffu, v, o);
    if (lane == 0) red[wrp] = v;
    __syncthreads();
    if (tid == 0) {
        float tt = 0.f;
        #pragma unroll
        for (int w = 0; w < 8; w++) tt += red[w];
        g_lossbt[b*nsamp + t] = tt * (1.0f/TY);
        g_valid[b*nsamp + t] = anyv;
    }
}

// ---------------- K5: deterministic final reduction ----------------
__global__ void k_final(float* __restrict__ out, int n)
{
    if (threadIdx.x == 0 && blockIdx.x == 0) {
        float tot = 0.f; int cnt = 0;
        for (int i = 0; i < n; i++) {
            if (g_valid[i]) { tot += g_lossbt[i]; cnt++; }
        }
        out[0] = tot / (float)(cnt > 0 ? cnt : 1);
    }
}

// ---------------- launch ----------------
extern "C" void kernel_launch(void* const* d_in, const int* in_sizes, int n_in,
                              void* d_out, int out_size)
{
    const float* fps   = (const float*)d_in[0];
    const float* x     = (const float*)d_in[1];
    const float* y     = (const float*)d_in[2];
    const int*   steps = (const int*)  d_in[3];
    const float* W1    = (const float*)d_in[4];
    const float* b1    = (const float*)d_in[5];
    const float* gamma = (const float*)d_in[6];
    const float* beta  = (const float*)d_in[7];
    const float* W2    = (const float*)d_in[8];
    const float* b2    = (const float*)d_in[9];
    const float* Wq    = (const float*)d_in[10];
    const float* bq    = (const float*)d_in[11];
    const float* Wk    = (const float*)d_in[12];
    const float* bk    = (const float*)d_in[13];
    float* out = (float*)d_out;

    int nsamp = in_sizes[3];
    if (nsamp > NS_MAX) nsamp = NS_MAX;

    float* alpha = out + 1;
    float* eorig = out + 1 + (size_t)B*S*S;

    size_t mlp_smem = (size_t)MLP_SMEM_FLOATS * sizeof(float);
    cudaFuncSetAttribute(k_mlp, cudaFuncAttributeMaxDynamicSharedMemorySize, (int)mlp_smem);

    k_mlp  <<< (B*S)/POSB, 256, mlp_smem >>>(fps, W1, b1, gamma, beta, W2, b2, Wq, bq, Wk, bk, eorig);
    k_gram <<< B*S, 256 >>>(x, y);
    k_attn <<< dim3(S/QC, B), 256 >>>(alpha);
    k_wpart<<< dim3(nsamp, B, CH), 256 >>>(steps, alpha, nsamp);
    k_solve2<<< dim3(nsamp, B), 256 >>>(x, y, steps, nsamp);
    k_final<<< 1, 32 >>>(out, B*nsamp);
}